// round 1
// baseline (speedup 1.0000x reference)
#include <cuda_runtime.h>

#define Bsz 64
#define Nq  256
#define Mn  1000
#define Sn  500
#define Hh  8
#define Dd  16

// ------------------- scratch (device globals; no allocation allowed) ----------
__device__ float g_q[Bsz*Nq*128];       // q projection  [B,N,H*D]
__device__ float g_concat[Bsz*Nq*128];  // mha1+mha2     [B,N,H*D]
__device__ float g_mh[Bsz*Nq*128];      // combine out   [B,N,E]
__device__ float g_rinv[Bsz*Nq];        // 1/rowsum for final softmax

// ------------------- generic row-tile GEMM: out[r][c] = sum_e in[r][e]*W[c][e]
// which==0: in = in_p (+extra col at e==128), out = g_q   (K=129)
// which==1: in = g_concat,                    out = g_mh  (K=128)
#define GROWS 64
__global__ __launch_bounds__(256,1)
void gemm_kernel(const float* __restrict__ in_p, const float* __restrict__ extra,
                 const float* __restrict__ W, int K, int which)
{
    extern __shared__ float sm[];
    float* xs = sm;               // 64*133
    float* ws = sm + GROWS*133;   // 128*133
    const float* in  = which ? g_concat : in_p;
    float*       out = which ? g_mh     : g_q;
    int row0 = blockIdx.x * GROWS;
    int t = threadIdx.x;

    for (int i = t; i < GROWS*K; i += 256) {
        int r = i / K, e = i - r*K;
        float v = (e < 128) ? in[(row0 + r)*128 + e] : extra[row0 + r];
        xs[r*133 + e] = v;
    }
    for (int i = t; i < 128*K; i += 256) {
        int c = i / K, e = i - c*K;
        ws[c*133 + e] = W[c*K + e];
    }
    __syncthreads();

    int tx = t & 15, ty = t >> 4;
    int r0 = ty*4;
    float acc[4][8];
    #pragma unroll
    for (int j=0;j<4;++j)
        #pragma unroll
        for (int i=0;i<8;++i) acc[j][i]=0.f;

    #pragma unroll 4
    for (int e = 0; e < K; ++e) {
        float a0 = xs[(r0+0)*133+e];
        float a1 = xs[(r0+1)*133+e];
        float a2 = xs[(r0+2)*133+e];
        float a3 = xs[(r0+3)*133+e];
        #pragma unroll
        for (int i=0;i<8;++i) {
            float w = ws[(tx + 16*i)*133 + e];
            acc[0][i] += a0*w; acc[1][i] += a1*w;
            acc[2][i] += a2*w; acc[3][i] += a3*w;
        }
    }
    #pragma unroll
    for (int j=0;j<4;++j)
        #pragma unroll
        for (int i=0;i<8;++i)
            out[(row0 + r0 + j)*128 + tx + 16*i] = acc[j][i];
}

// ------------------- fused dual attention --------------------------------
// block = (b, 64-query tile), 512 threads, thread = (head h, query n)
#define LC 64
#define NT 64
__global__ __launch_bounds__(512,1)
void attn_kernel(const float* __restrict__ kg0, const float* __restrict__ vg0,
                 const float* __restrict__ kg1, const float* __restrict__ vg1,
                 const float* __restrict__ mg0, const float* __restrict__ mg1)
{
    extern __shared__ float sm[];
    float* k_s = sm;             // 8*LC*16 = 8192 floats
    float* v_s = sm + 8192;      // 8192 floats
    float* m_s = sm + 16384;     // LC*65 = 4160 floats (transposed, padded)

    int b  = blockIdx.x >> 2;
    int n0 = (blockIdx.x & 3) * NT;
    int t  = threadIdx.x;
    int h  = t >> 6, n = t & 63;
    int row = b*Nq + n0 + n;

    const float4* gq4 = (const float4*)g_q;
    float4 q0 = gq4[row*32 + h*4 + 0];
    float4 q1 = gq4[row*32 + h*4 + 1];
    float4 q2 = gq4[row*32 + h*4 + 2];
    float4 q3 = gq4[row*32 + h*4 + 3];
    const float sc = 0.25f;   // 1/sqrt(D), D=16
    q0.x*=sc; q0.y*=sc; q0.z*=sc; q0.w*=sc;
    q1.x*=sc; q1.y*=sc; q1.z*=sc; q1.w*=sc;
    q2.x*=sc; q2.y*=sc; q2.z*=sc; q2.w*=sc;
    q3.x*=sc; q3.y*=sc; q3.z*=sc; q3.w*=sc;

    float res[16];
    #pragma unroll
    for (int i=0;i<16;++i) res[i]=0.f;

    for (int pass = 0; pass < 2; ++pass) {
        const float* kg = pass ? kg1 : kg0;
        const float* vg = pass ? vg1 : vg0;
        const float* mg = pass ? mg1 : mg0;
        int L = pass ? Sn : Mn;

        float acc[16];
        #pragma unroll
        for (int i=0;i<16;++i) acc[i]=0.f;
        float lsum = 0.f;

        for (int l0 = 0; l0 < L; l0 += LC) {
            int lc = min(LC, L - l0);
            __syncthreads();
            const float4* kg4 = (const float4*)kg;
            const float4* vg4 = (const float4*)vg;
            for (int i = t; i < 2048; i += 512) {
                int hh = i >> 8; int l = (i >> 2) & 63;
                if (l < lc) {
                    int g = ((b*8 + hh)*L + l0 + l)*4 + (i & 3);
                    ((float4*)k_s)[i] = kg4[g];
                    ((float4*)v_s)[i] = vg4[g];
                }
            }
            for (int i = t; i < NT*LC; i += 512) {
                int nn = i >> 6; int l = i & 63;
                if (l < lc)
                    m_s[l*65 + nn] = mg[(b*Nq + n0 + nn)*L + l0 + l];
            }
            __syncthreads();

            const float4* kp = (const float4*)k_s + h*(LC*4);
            const float4* vp = (const float4*)v_s + h*(LC*4);
            #pragma unroll 2
            for (int l = 0; l < lc; ++l) {
                float4 a0 = kp[l*4+0], a1 = kp[l*4+1], a2 = kp[l*4+2], a3 = kp[l*4+3];
                float s;
                s  = q0.x*a0.x + q0.y*a0.y + q0.z*a0.z + q0.w*a0.w;
                s += q1.x*a1.x + q1.y*a1.y + q1.z*a1.z + q1.w*a1.w;
                s += q2.x*a2.x + q2.y*a2.y + q2.z*a2.z + q2.w*a2.w;
                s += q3.x*a3.x + q3.y*a3.y + q3.z*a3.z + q3.w*a3.w;
                float p = __expf(s + m_s[l*65 + n]);   // mask = 0 or -1e9; no max needed
                lsum += p;
                float4 b0 = vp[l*4+0], b1 = vp[l*4+1], b2 = vp[l*4+2], b3 = vp[l*4+3];
                acc[0]  += p*b0.x; acc[1]  += p*b0.y; acc[2]  += p*b0.z; acc[3]  += p*b0.w;
                acc[4]  += p*b1.x; acc[5]  += p*b1.y; acc[6]  += p*b1.z; acc[7]  += p*b1.w;
                acc[8]  += p*b2.x; acc[9]  += p*b2.y; acc[10] += p*b2.z; acc[11] += p*b2.w;
                acc[12] += p*b3.x; acc[13] += p*b3.y; acc[14] += p*b3.z; acc[15] += p*b3.w;
            }
        }
        float inv = 1.f / lsum;
        #pragma unroll
        for (int i=0;i<16;++i) res[i] += acc[i]*inv;
    }

    float4* og = (float4*)g_concat;
    og[row*32 + h*4 + 0] = make_float4(res[0], res[1], res[2], res[3]);
    og[row*32 + h*4 + 1] = make_float4(res[4], res[5], res[6], res[7]);
    og[row*32 + h*4 + 2] = make_float4(res[8], res[9], res[10], res[11]);
    og[row*32 + h*4 + 3] = make_float4(res[12], res[13], res[14], res[15]);
}

// ------------------- score GEMM + tanh clip + mask + exp + rowsum ---------
// block = (b, 64-query tile), 256 threads, thread-tile 4n x 4m
__global__ __launch_bounds__(256,1)
void score_kernel(const float* __restrict__ shk, const float* __restrict__ ninf,
                  float* __restrict__ out)
{
    extern __shared__ float sm[];
    float* mh_s = sm;            // 64*128 = 8192
    float* sk_s = sm + 8192;     // 128*64 = 8192

    int b  = blockIdx.x >> 2;
    int n0 = (blockIdx.x & 3) * 64;
    int t  = threadIdx.x;
    int tx = t & 15, ty = t >> 4;

    for (int i = t; i < 2048; i += 256)
        ((float4*)mh_s)[i] = ((const float4*)g_mh)[(b*Nq + n0 + (i>>5))*32 + (i & 31)];
    __syncthreads();

    float psum[4] = {0.f, 0.f, 0.f, 0.f};
    const float invSE = (float)(1.0/11.313708498984761);

    for (int m0 = 0; m0 < Mn; m0 += 64) {
        int mc = min(64, Mn - m0);
        __syncthreads();
        for (int i = t; i < 8192; i += 256) {
            int e = i >> 6, m = i & 63;
            sk_s[i] = (m < mc) ? shk[(b*128 + e)*Mn + m0 + m] : 0.f;
        }
        __syncthreads();

        float c[4][4];
        #pragma unroll
        for (int j=0;j<4;++j)
            #pragma unroll
            for (int i=0;i<4;++i) c[j][i]=0.f;

        #pragma unroll 4
        for (int e = 0; e < 128; ++e) {
            float a0 = mh_s[(ty*4+0)*128+e];
            float a1 = mh_s[(ty*4+1)*128+e];
            float a2 = mh_s[(ty*4+2)*128+e];
            float a3 = mh_s[(ty*4+3)*128+e];
            float4 w = ((const float4*)sk_s)[e*16 + tx];
            c[0][0]+=a0*w.x; c[0][1]+=a0*w.y; c[0][2]+=a0*w.z; c[0][3]+=a0*w.w;
            c[1][0]+=a1*w.x; c[1][1]+=a1*w.y; c[1][2]+=a1*w.z; c[1][3]+=a1*w.w;
            c[2][0]+=a2*w.x; c[2][1]+=a2*w.y; c[2][2]+=a2*w.z; c[2][3]+=a2*w.w;
            c[3][0]+=a3*w.x; c[3][1]+=a3*w.y; c[3][2]+=a3*w.z; c[3][3]+=a3*w.w;
        }

        int mbase = m0 + tx*4;
        if (mbase < Mn) {   // Mn % 4 == 0 -> full float4 or nothing
            #pragma unroll
            for (int j=0;j<4;++j) {
                int rown = b*Nq + n0 + ty*4 + j;
                float4 msk = ((const float4*)ninf)[rown*250 + (mbase>>2)];
                float4 p;
                {
                    float xx = c[j][0]*invSE;
                    float th = 1.f - __fdividef(2.f, __expf(2.f*xx) + 1.f);
                    p.x = __expf(10.f*th + msk.x);
                }
                {
                    float xx = c[j][1]*invSE;
                    float th = 1.f - __fdividef(2.f, __expf(2.f*xx) + 1.f);
                    p.y = __expf(10.f*th + msk.y);
                }
                {
                    float xx = c[j][2]*invSE;
                    float th = 1.f - __fdividef(2.f, __expf(2.f*xx) + 1.f);
                    p.z = __expf(10.f*th + msk.z);
                }
                {
                    float xx = c[j][3]*invSE;
                    float th = 1.f - __fdividef(2.f, __expf(2.f*xx) + 1.f);
                    p.w = __expf(10.f*th + msk.w);
                }
                ((float4*)out)[rown*250 + (mbase>>2)] = p;
                psum[j] += (p.x + p.y) + (p.z + p.w);
            }
        }
    }

    // reduce row sums across the 16 lanes sharing each (ty, j) row
    #pragma unroll
    for (int j=0;j<4;++j) {
        float v = psum[j];
        v += __shfl_xor_sync(0xffffffffu, v, 1);
        v += __shfl_xor_sync(0xffffffffu, v, 2);
        v += __shfl_xor_sync(0xffffffffu, v, 4);
        v += __shfl_xor_sync(0xffffffffu, v, 8);
        if (tx == 0)
            g_rinv[b*Nq + n0 + ty*4 + j] = 1.f / v;
    }
}

// ------------------- final normalize -------------------------------------
__global__ void norm_kernel(float* __restrict__ out)
{
    int i = blockIdx.x*256 + threadIdx.x;        // float4 index
    if (i < (Bsz*Nq*Mn)/4) {
        float inv = g_rinv[i / 250];
        float4 v = ((float4*)out)[i];
        v.x *= inv; v.y *= inv; v.z *= inv; v.w *= inv;
        ((float4*)out)[i] = v;
    }
}

// ------------------- launch ----------------------------------------------
extern "C" void kernel_launch(void* const* d_in, const int* in_sizes, int n_in,
                              void* d_out, int out_size)
{
    const float* enc   = (const float*)d_in[0];
    const float* loadv = (const float*)d_in[1];
    const float* sols  = (const float*)d_in[2];
    const float* ninf  = (const float*)d_in[3];
    const float* k     = (const float*)d_in[4];
    const float* v     = (const float*)d_in[5];
    const float* ksol  = (const float*)d_in[6];
    const float* vsol  = (const float*)d_in[7];
    const float* shk   = (const float*)d_in[8];
    const float* Wq    = (const float*)d_in[9];
    const float* Wc    = (const float*)d_in[10];
    float* out = (float*)d_out;

    const int GEMM_SMEM  = (GROWS + 128) * 133 * 4;          // 102,144 B
    const int ATTN_SMEM  = (8192 + 8192 + LC*65) * 4;        //  82,176 B
    const int SCORE_SMEM = (8192 + 8192) * 4;                //  65,536 B
    cudaFuncSetAttribute(gemm_kernel,  cudaFuncAttributeMaxDynamicSharedMemorySize, GEMM_SMEM);
    cudaFuncSetAttribute(attn_kernel,  cudaFuncAttributeMaxDynamicSharedMemorySize, ATTN_SMEM);
    cudaFuncSetAttribute(score_kernel, cudaFuncAttributeMaxDynamicSharedMemorySize, SCORE_SMEM);

    // 1) q projection: [B*N,129] x [129,128]
    gemm_kernel<<<(Bsz*Nq)/GROWS, 256, GEMM_SMEM>>>(enc, loadv, Wq, 129, 0);
    // 2) dual attention -> g_concat
    attn_kernel<<<Bsz*(Nq/NT), 512, ATTN_SMEM>>>(k, v, ksol, vsol, ninf, sols);
    // 3) combine: [B*N,128] x [128,128]
    gemm_kernel<<<(Bsz*Nq)/GROWS, 256, GEMM_SMEM>>>(nullptr, nullptr, Wc, 128, 1);
    // 4) score + tanh clip + mask + exp + rowsums
    score_kernel<<<Bsz*(Nq/64), 256, SCORE_SMEM>>>(shk, ninf, out);
    // 5) normalize
    norm_kernel<<<(Bsz*Nq*Mn)/4/256, 256>>>(out);
}

// round 4
// speedup vs baseline: 1.1377x; 1.1377x over previous
#include <cuda_runtime.h>

#define Bsz 64
#define Nq  256
#define Mn  1000
#define Sn  500

typedef unsigned long long u64t;

__device__ __forceinline__ u64t ffma2(u64t a, u64t b, u64t c) {
    u64t d;
    asm("fma.rn.f32x2 %0, %1, %2, %3;" : "=l"(d) : "l"(a), "l"(b), "l"(c));
    return d;
}
__device__ __forceinline__ u64t pk2(float lo, float hi) {
    u64t r;
    asm("mov.b64 %0, {%1, %2};" : "=l"(r) : "f"(lo), "f"(hi));
    return r;
}
__device__ __forceinline__ float2 upk2(u64t v) {
    float2 f;
    asm("mov.b64 {%0, %1}, %2;" : "=f"(f.x), "=f"(f.y) : "l"(v));
    return f;
}

// ------------------- scratch ------------------------------------------------
__device__ float g_q[Bsz*Nq*128];        // q projection  [B,N,H*D]
__device__ float g_concat[Bsz*Nq*128];   // mha1+mha2     [B,N,H*D]
__device__ float g_mh[Bsz*Nq*128];       // combine out   [B,N,E]
__device__ float g_rinv[Bsz*Nq];         // 1/rowsum for final softmax
__device__ float g_pacc[3*Bsz*Nq*8*16];  // attn partial accumulators
__device__ float g_psum[3*Bsz*Nq*8];     // attn partial exp-sums

// ------------------- generic row-tile GEMM ---------------------------------
#define GROWS 64
__global__ __launch_bounds__(256,1)
void gemm_kernel(const float* __restrict__ in_p, const float* __restrict__ extra,
                 const float* __restrict__ W, int K, int which)
{
    extern __shared__ float sm[];
    float* xs = sm;               // 64*133
    float* ws = sm + GROWS*133;   // 128*133
    const float* in  = which ? g_concat : in_p;
    float*       out = which ? g_mh     : g_q;
    int row0 = blockIdx.x * GROWS;
    int t = threadIdx.x;

    for (int i = t; i < GROWS*K; i += 256) {
        int r = i / K, e = i - r*K;
        float v = (e < 128) ? in[(row0 + r)*128 + e] : extra[row0 + r];
        xs[r*133 + e] = v;
    }
    for (int i = t; i < 128*K; i += 256) {
        int c = i / K, e = i - c*K;
        ws[c*133 + e] = W[c*K + e];
    }
    __syncthreads();

    int tx = t & 15, ty = t >> 4;
    int r0 = ty*4;
    float acc[4][8];
    #pragma unroll
    for (int j=0;j<4;++j)
        #pragma unroll
        for (int i=0;i<8;++i) acc[j][i]=0.f;

    #pragma unroll 4
    for (int e = 0; e < K; ++e) {
        float a0 = xs[(r0+0)*133+e];
        float a1 = xs[(r0+1)*133+e];
        float a2 = xs[(r0+2)*133+e];
        float a3 = xs[(r0+3)*133+e];
        #pragma unroll
        for (int i=0;i<8;++i) {
            float w = ws[(tx + 16*i)*133 + e];
            acc[0][i] += a0*w; acc[1][i] += a1*w;
            acc[2][i] += a2*w; acc[3][i] += a3*w;
        }
    }
    #pragma unroll
    for (int j=0;j<4;++j)
        #pragma unroll
        for (int i=0;i<8;++i)
            out[(row0 + r0 + j)*128 + tx + 16*i] = acc[j][i];
}

// ------------------- fused dual attention (partials) -----------------------
// grid: 64 b x 4 ntiles x 3 chunks.  block: 128 threads = 8 heads x 16 groups,
// each thread handles 4 queries (strided by 16) -> 4x LDS amortization.
// chunk 0: keys[0,500) of pass0; chunk 1: keys[500,1000) of pass0;
// chunk 2: keys[0,500) of pass1.  Softmax has no max-subtraction (scores tiny,
// mask additive -1e9 -> exp underflows to 0), so partials combine linearly.
#define LCH 32
__global__ __launch_bounds__(128,1)
void attn_kernel(const float* __restrict__ kg0, const float* __restrict__ vg0,
                 const float* __restrict__ kg1, const float* __restrict__ vg1,
                 const float* __restrict__ mg0, const float* __restrict__ mg1)
{
    extern __shared__ float sm[];
    float* k_s = sm;             // 8h*32l*16d = 4096 floats
    float* v_s = sm + 4096;      // 4096 floats
    float* m_s = sm + 8192;      // 64n * 33 (padded) floats

    int c  = blockIdx.x % 3;
    int rb = blockIdx.x / 3;
    int n0 = (rb & 3) << 6;
    int b  = rb >> 2;

    const float* kg = (c==2) ? kg1 : kg0;
    const float* vg = (c==2) ? vg1 : vg0;
    const float* mg = (c==2) ? mg1 : mg0;
    int Lfull = (c==2) ? Sn : Mn;
    int lbase = (c==1) ? 500 : 0;

    int t = threadIdx.x;
    int h = t >> 4, g = t & 15;

    u64t q2[4][8], acc2[4][8];
    float lsum[4];
    const float4* gq4 = (const float4*)g_q;
    #pragma unroll
    for (int qi=0; qi<4; ++qi) {
        int row = b*Nq + n0 + g + 16*qi;
        #pragma unroll
        for (int j=0; j<4; ++j) {
            float4 qv = gq4[row*32 + h*4 + j];
            q2[qi][2*j]   = pk2(qv.x*0.25f, qv.y*0.25f);   // 1/sqrt(16)
            q2[qi][2*j+1] = pk2(qv.z*0.25f, qv.w*0.25f);
        }
        #pragma unroll
        for (int i=0; i<8; ++i) acc2[qi][i] = pk2(0.f, 0.f);
        lsum[qi] = 0.f;
    }

    const float4* kg4 = (const float4*)kg;
    const float4* vg4 = (const float4*)vg;
    float4* k_s4 = (float4*)k_s;
    float4* v_s4 = (float4*)v_s;

    for (int l0 = 0; l0 < 500; l0 += LCH) {
        int lc = min(LCH, 500 - l0);
        __syncthreads();
        #pragma unroll
        for (int ii=0; ii<8; ++ii) {
            int i = t + ii*128;               // i = hh*128 + l*4 + d4
            int hh = i >> 7, l = (i >> 2) & 31, d4 = i & 3;
            if (l < lc) {
                int gi = ((b*8 + hh)*Lfull + lbase + l0 + l)*4 + d4;
                k_s4[i] = kg4[gi];
                v_s4[i] = vg4[gi];
            }
        }
        #pragma unroll
        for (int ii=0; ii<16; ++ii) {
            int i = t + ii*128;               // i = n*32 + l
            int n = i >> 5, l = i & 31;
            if (l < lc)
                m_s[n*33 + l] = mg[(b*Nq + n0 + n)*Lfull + lbase + l0 + l];
        }
        __syncthreads();

        const float4* kp = k_s4 + h*128;
        const float4* vp = v_s4 + h*128;
        #pragma unroll 2
        for (int l = 0; l < lc; ++l) {
            float4 a0 = kp[l*4+0], a1 = kp[l*4+1], a2 = kp[l*4+2], a3 = kp[l*4+3];
            u64t kk0 = pk2(a0.x,a0.y), kk1 = pk2(a0.z,a0.w);
            u64t kk2 = pk2(a1.x,a1.y), kk3 = pk2(a1.z,a1.w);
            u64t kk4 = pk2(a2.x,a2.y), kk5 = pk2(a2.z,a2.w);
            u64t kk6 = pk2(a3.x,a3.y), kk7 = pk2(a3.z,a3.w);
            float p[4];
            #pragma unroll
            for (int qi=0; qi<4; ++qi) {
                u64t s2 = pk2(0.f, 0.f);
                s2 = ffma2(q2[qi][0], kk0, s2);
                s2 = ffma2(q2[qi][1], kk1, s2);
                s2 = ffma2(q2[qi][2], kk2, s2);
                s2 = ffma2(q2[qi][3], kk3, s2);
                s2 = ffma2(q2[qi][4], kk4, s2);
                s2 = ffma2(q2[qi][5], kk5, s2);
                s2 = ffma2(q2[qi][6], kk6, s2);
                s2 = ffma2(q2[qi][7], kk7, s2);
                float2 sf = upk2(s2);
                p[qi] = __expf(sf.x + sf.y + m_s[(g + 16*qi)*33 + l]);
                lsum[qi] += p[qi];
            }
            float4 b0 = vp[l*4+0], b1 = vp[l*4+1], b2 = vp[l*4+2], b3 = vp[l*4+3];
            u64t vv0 = pk2(b0.x,b0.y), vv1 = pk2(b0.z,b0.w);
            u64t vv2 = pk2(b1.x,b1.y), vv3 = pk2(b1.z,b1.w);
            u64t vv4 = pk2(b2.x,b2.y), vv5 = pk2(b2.z,b2.w);
            u64t vv6 = pk2(b3.x,b3.y), vv7 = pk2(b3.z,b3.w);
            #pragma unroll
            for (int qi=0; qi<4; ++qi) {
                u64t pp = pk2(p[qi], p[qi]);
                acc2[qi][0] = ffma2(pp, vv0, acc2[qi][0]);
                acc2[qi][1] = ffma2(pp, vv1, acc2[qi][1]);
                acc2[qi][2] = ffma2(pp, vv2, acc2[qi][2]);
                acc2[qi][3] = ffma2(pp, vv3, acc2[qi][3]);
                acc2[qi][4] = ffma2(pp, vv4, acc2[qi][4]);
                acc2[qi][5] = ffma2(pp, vv5, acc2[qi][5]);
                acc2[qi][6] = ffma2(pp, vv6, acc2[qi][6]);
                acc2[qi][7] = ffma2(pp, vv7, acc2[qi][7]);
            }
        }
    }

    // write partials
    float4* pacc4 = (float4*)g_pacc;
    const int STR = Bsz*Nq*8;
    #pragma unroll
    for (int qi=0; qi<4; ++qi) {
        int rr = (b*Nq + n0 + g + 16*qi)*8 + h;
        int base = (c*STR + rr)*4;
        #pragma unroll
        for (int j=0; j<4; ++j) {
            float2 e0 = upk2(acc2[qi][2*j]);
            float2 e1 = upk2(acc2[qi][2*j+1]);
            pacc4[base + j] = make_float4(e0.x, e0.y, e1.x, e1.y);
        }
        g_psum[c*STR + rr] = lsum[qi];
    }
}

// ------------------- combine attn partials ---------------------------------
__global__ void reduce_kernel()
{
    int i = blockIdx.x*256 + threadIdx.x;       // over Bsz*Nq*8*4 float4s
    const int STR = Bsz*Nq*8;
    if (i >= STR*4) return;
    int r = i >> 2, col = i & 3;
    const float4* pacc4 = (const float4*)g_pacc;
    float4 a0 = pacc4[(0*STR + r)*4 + col];
    float4 a1 = pacc4[(1*STR + r)*4 + col];
    float4 a2 = pacc4[(2*STR + r)*4 + col];
    float inv01 = 1.f / (g_psum[r] + g_psum[STR + r]);
    float inv2  = 1.f /  g_psum[2*STR + r];
    float4 o;
    o.x = (a0.x + a1.x)*inv01 + a2.x*inv2;
    o.y = (a0.y + a1.y)*inv01 + a2.y*inv2;
    o.z = (a0.z + a1.z)*inv01 + a2.z*inv2;
    o.w = (a0.w + a1.w)*inv01 + a2.w*inv2;
    int bn = r >> 3, h = r & 7;
    ((float4*)g_concat)[bn*32 + h*4 + col] = o;
}

// ------------------- score GEMM + tanh clip + mask + exp + rowsum ----------
// grid 128 = 64 b x 2 ntiles (128 rows each) -> one wave on 148 SMs.
// 256 threads, thread tile 8 rows x 8 cols (cols as 4 packed pairs (m, m+16)).
__global__ __launch_bounds__(256,1)
void score_kernel(const float* __restrict__ shk, const float* __restrict__ ninf,
                  float* __restrict__ out)
{
    extern __shared__ float sm[];
    float* mh_s = sm;                       // 128 rows x 132 (padded)
    u64t*  sk2  = (u64t*)(sm + 128*132);    // 128 e x 64 packed col-pairs

    int b  = blockIdx.x >> 1;
    int n0 = (blockIdx.x & 1) << 7;
    int t  = threadIdx.x, tx = t & 15, ty = t >> 4;

    // stage mh rows (once)
    #pragma unroll
    for (int ii=0; ii<16; ++ii) {
        int i = t + ii*256;                 // float4 index of [128][128]
        int r = i >> 5, c4 = i & 31;
        float4 v = ((const float4*)g_mh)[(b*Nq + n0 + r)*32 + c4];
        *(float4*)&mh_s[r*132 + c4*4] = v;  // 132*4 = 528 = 33*16 -> aligned
    }

    float psum[8];
    #pragma unroll
    for (int j=0;j<8;++j) psum[j]=0.f;
    const float invSE = 0.08838834764831845f;   // 1/sqrt(128)

    for (int m0 = 0; m0 < Mn; m0 += 128) {
        __syncthreads();
        #pragma unroll
        for (int ii=0; ii<32; ++ii) {
            int i = t + ii*256;             // i = e*64 + p
            int e = i >> 6, p = i & 63;
            int lo = m0 + (p & 15) + 32*(p >> 4);
            float flo = (lo      < Mn) ? shk[(b*128 + e)*Mn + lo]      : 0.f;
            float fhi = (lo + 16 < Mn) ? shk[(b*128 + e)*Mn + lo + 16] : 0.f;
            sk2[i] = pk2(flo, fhi);
        }
        __syncthreads();

        u64t c2[8][4];
        #pragma unroll
        for (int j=0;j<8;++j)
            #pragma unroll
            for (int i2=0;i2<4;++i2) c2[j][i2] = pk2(0.f, 0.f);

        #pragma unroll 2
        for (int e = 0; e < 128; ++e) {
            u64t w0 = sk2[e*64 + tx];
            u64t w1 = sk2[e*64 + tx + 16];
            u64t w2 = sk2[e*64 + tx + 32];
            u64t w3 = sk2[e*64 + tx + 48];
            #pragma unroll
            for (int j=0; j<8; ++j) {
                float a = mh_s[(ty + 16*j)*132 + e];
                u64t a2 = pk2(a, a);
                c2[j][0] = ffma2(a2, w0, c2[j][0]);
                c2[j][1] = ffma2(a2, w1, c2[j][1]);
                c2[j][2] = ffma2(a2, w2, c2[j][2]);
                c2[j][3] = ffma2(a2, w3, c2[j][3]);
            }
        }

        #pragma unroll
        for (int j=0; j<8; ++j) {
            int row = b*Nq + n0 + ty + 16*j;
            #pragma unroll
            for (int i2=0; i2<4; ++i2) {
                float2 cv = upk2(c2[j][i2]);
                int mlo = m0 + tx + 32*i2;
                int mhi = mlo + 16;
                if (mlo < Mn) {
                    float xx = cv.x * invSE;
                    float th = 1.f - __fdividef(2.f, __expf(2.f*xx) + 1.f);
                    float pv = __expf(10.f*th + ninf[row*Mn + mlo]);
                    out[row*Mn + mlo] = pv;
                    psum[j] += pv;
                }
                if (mhi < Mn) {
                    float xx = cv.y * invSE;
                    float th = 1.f - __fdividef(2.f, __expf(2.f*xx) + 1.f);
                    float pv = __expf(10.f*th + ninf[row*Mn + mhi]);
                    out[row*Mn + mhi] = pv;
                    psum[j] += pv;
                }
            }
        }
    }

    #pragma unroll
    for (int j=0; j<8; ++j) {
        float v = psum[j];
        v += __shfl_xor_sync(0xffffffffu, v, 1);
        v += __shfl_xor_sync(0xffffffffu, v, 2);
        v += __shfl_xor_sync(0xffffffffu, v, 4);
        v += __shfl_xor_sync(0xffffffffu, v, 8);
        if (tx == 0)
            g_rinv[b*Nq + n0 + ty + 16*j] = 1.f / v;
    }
}

// ------------------- final normalize ---------------------------------------
__global__ void norm_kernel(float* __restrict__ out)
{
    int i = blockIdx.x*256 + threadIdx.x;        // float4 index
    if (i < (Bsz*Nq*Mn)/4) {
        float inv = g_rinv[i / 250];
        float4 v = ((float4*)out)[i];
        v.x *= inv; v.y *= inv; v.z *= inv; v.w *= inv;
        ((float4*)out)[i] = v;
    }
}

// ------------------- launch -------------------------------------------------
extern "C" void kernel_launch(void* const* d_in, const int* in_sizes, int n_in,
                              void* d_out, int out_size)
{
    const float* enc   = (const float*)d_in[0];
    const float* loadv = (const float*)d_in[1];
    const float* sols  = (const float*)d_in[2];
    const float* ninf  = (const float*)d_in[3];
    const float* k     = (const float*)d_in[4];
    const float* v     = (const float*)d_in[5];
    const float* ksol  = (const float*)d_in[6];
    const float* vsol  = (const float*)d_in[7];
    const float* shk   = (const float*)d_in[8];
    const float* Wq    = (const float*)d_in[9];
    const float* Wc    = (const float*)d_in[10];
    float* out = (float*)d_out;

    const int GEMM_SMEM  = (GROWS + 128) * 133 * 4;            // 102,144 B
    const int ATTN_SMEM  = (4096 + 4096 + 64*33) * 4;          //  41,216 B
    const int SCORE_SMEM = (128*132)*4 + 128*64*8;             // 133,120 B
    cudaFuncSetAttribute(gemm_kernel,  cudaFuncAttributeMaxDynamicSharedMemorySize, GEMM_SMEM);
    cudaFuncSetAttribute(attn_kernel,  cudaFuncAttributeMaxDynamicSharedMemorySize, ATTN_SMEM);
    cudaFuncSetAttribute(score_kernel, cudaFuncAttributeMaxDynamicSharedMemorySize, SCORE_SMEM);

    // 1) q projection: [B*N,129] x [129,128]
    gemm_kernel<<<(Bsz*Nq)/GROWS, 256, GEMM_SMEM>>>(enc, loadv, Wq, 129, 0);
    // 2) dual attention partials (3 key-chunks)
    attn_kernel<<<Bsz*4*3, 128, ATTN_SMEM>>>(k, v, ksol, vsol, ninf, sols);
    // 3) combine partials -> g_concat
    reduce_kernel<<<(Bsz*Nq*8*4)/256, 256>>>();
    // 4) combine GEMM: [B*N,128] x [128,128]
    gemm_kernel<<<(Bsz*Nq)/GROWS, 256, GEMM_SMEM>>>(nullptr, nullptr, Wc, 128, 1);
    // 5) score + tanh clip + mask + exp + rowsums
    score_kernel<<<Bsz*2, 256, SCORE_SMEM>>>(shk, ninf, out);
    // 6) normalize
    norm_kernel<<<(Bsz*Nq*Mn)/4/256, 256>>>(out);
}